// round 16
// baseline (speedup 1.0000x reference)
#include <cuda_runtime.h>
#include <cuda_bf16.h>
#include <mma.h>
#include <cstdint>

using namespace nvcuda;

#define D 64
#define KC 400
#define MTILE 128
#define NCH 80
#define NCHUNKS 5
#define TPB 256
#define XTLD 136        // bf16 ld for xT tiles [d][row]
#define ELD2 72         // bf16 ld for e tiles [code][d]
#define SCLD 20         // f32 ld for per-warp 16x16 score scratch (mult of 4)

// smem byte offsets
#define OFF_XTH 0                   // bf16[64][136] x3 (xT splits, persist)
#define OFF_XTM 17408
#define OFF_XTL 34816
#define OFF_EH  52224               // bf16[80][72] x3
#define OFF_EM  63744
#define OFF_EL  75264
#define OFF_SCR 86784               // f32[8 warps][16][20] = 10240 B
#define OFF_N2A 97024               // f32[400]
#define OFF_RW  98624               // int[128]
#define SMEM_BYTES 99200

// precomputed e splits (h,m,l) and norms — __device__ scratch (allowed)
__device__ __nv_bfloat16 g_esp[3][KC * D];
__device__ float g_n2[KC];

// 3-way bf16 split: a ~= h + m + l (each captures ~8 mantissa bits)
static __device__ __forceinline__ void split3(float a, __nv_bfloat16 &h,
                                              __nv_bfloat16 &m, __nv_bfloat16 &l) {
    h = __float2bfloat16(a);
    float r = a - __bfloat162float(h);
    m = __float2bfloat16(r);
    float r2 = r - __bfloat162float(m);
    l = __float2bfloat16(r2);
}

__global__ void vq_prep_kernel(const float* __restrict__ emb) {
    int i = blockIdx.x * blockDim.x + threadIdx.x;
    if (i < KC * D) {
        __nv_bfloat16 h, m, l;
        split3(emb[i], h, m, l);
        g_esp[0][i] = h;
        g_esp[1][i] = m;
        g_esp[2][i] = l;
    }
    if (i < KC) {
        const float* e = emb + (size_t)i * D;
        float s = 0.f;
        #pragma unroll 16
        for (int d = 0; d < D; d++) s = fmaf(e[d], e[d], s);
        g_n2[i] = -0.5f * s;
    }
}

__global__ void __launch_bounds__(TPB, 2)
vq_wmma_kernel(const float* __restrict__ x, const float* __restrict__ emb,
               float* __restrict__ out, int nrows) {
    extern __shared__ char sm[];
    float* n2a = (float*)(sm + OFF_N2A);
    int*   rw  = (int*)(sm + OFF_RW);

    const int tid = threadIdx.x;
    const int wid = tid >> 5;
    const int lane = tid & 31;
    const int row0 = blockIdx.x * MTILE;

    // ---- norms to smem (precomputed) ----
    for (int i = tid; i < KC; i += TPB) n2a[i] = g_n2[i];

    // ---- stage xT once: [d][row] x3 splits; row-inner -> coalesced STS ----
    {
        const float4* xg = (const float4*)(x + (size_t)row0 * D);
        __nv_bfloat16* xth = (__nv_bfloat16*)(sm + OFF_XTH);
        __nv_bfloat16* xtm = (__nv_bfloat16*)(sm + OFF_XTM);
        __nv_bfloat16* xtl = (__nv_bfloat16*)(sm + OFF_XTL);
        for (int i = tid; i < MTILE * 16; i += TPB) {
            int row = i & 127, db = i >> 7;
            float4 v = xg[row * 16 + db];
            float vv[4] = {v.x, v.y, v.z, v.w};
            #pragma unroll
            for (int cc = 0; cc < 4; cc++) {
                __nv_bfloat16 h, m, l;
                split3(vv[cc], h, m, l);
                int o = (4 * db + cc) * XTLD + row;
                xth[o] = h; xtm[o] = m; xtl[o] = l;
            }
        }
    }

    // warp-private scan state: lane (r,h) owns x-row wid*16+r, code-half h
    const int r = lane >> 1;
    const int h = lane & 1;
    float best = -3.4e38f;
    int bidx = 0;
    float* swp = (float*)(sm + OFF_SCR) + wid * (16 * SCLD);

    const __nv_bfloat16* eh  = (const __nv_bfloat16*)(sm + OFF_EH);
    const __nv_bfloat16* em  = (const __nv_bfloat16*)(sm + OFF_EM);
    const __nv_bfloat16* el  = (const __nv_bfloat16*)(sm + OFF_EL);
    const __nv_bfloat16* xth = (const __nv_bfloat16*)(sm + OFF_XTH) + wid * 16;
    const __nv_bfloat16* xtm = (const __nv_bfloat16*)(sm + OFF_XTM) + wid * 16;
    const __nv_bfloat16* xtl = (const __nv_bfloat16*)(sm + OFF_XTL) + wid * 16;

    for (int c = 0; c < NCHUNKS; c++) {
        const int g0 = c * NCH;
        __syncthreads();   // all warps done with chunk c-1 e-tiles

        // ---- stage e chunk: pure uint4 copies of precomputed splits ----
        for (int i = tid; i < 3 * NCH * 8; i += TPB) {
            int split = i / (NCH * 8);
            int idx = i - split * (NCH * 8);
            int code = idx >> 3, c8 = idx & 7;
            uint4 v = *(const uint4*)(&g_esp[split][(size_t)(g0 + code) * D + c8 * 8]);
            *(uint4*)(sm + OFF_EH + split * 11520 + (code * ELD2 + c8 * 8) * 2) = v;
        }
        __syncthreads();

        // ---- nf-outer: MMA 16 codes x all k, then WARP-LOCAL store+scan ----
        #pragma unroll
        for (int nf = 0; nf < 5; nf++) {
            wmma::fragment<wmma::accumulator, 16, 16, 16, float> acc;
            wmma::fill_fragment(acc, 0.0f);

            #pragma unroll
            for (int k = 0; k < 4; k++) {
                wmma::fragment<wmma::matrix_b, 16, 16, 16, __nv_bfloat16, wmma::row_major> bh, bm, bl;
                wmma::load_matrix_sync(bh, xth + k * 16 * XTLD, XTLD);
                wmma::load_matrix_sync(bm, xtm + k * 16 * XTLD, XTLD);
                wmma::load_matrix_sync(bl, xtl + k * 16 * XTLD, XTLD);
                wmma::fragment<wmma::matrix_a, 16, 16, 16, __nv_bfloat16, wmma::row_major> ah, am, al;
                wmma::load_matrix_sync(ah, eh + nf * 16 * ELD2 + k * 16, ELD2);
                wmma::load_matrix_sync(am, em + nf * 16 * ELD2 + k * 16, ELD2);
                wmma::load_matrix_sync(al, el + nf * 16 * ELD2 + k * 16, ELD2);
                wmma::mma_sync(acc, ah, bh, acc);   // hh
                wmma::mma_sync(acc, ah, bm, acc);   // hm
                wmma::mma_sync(acc, am, bh, acc);   // mh
                wmma::mma_sync(acc, am, bm, acc);   // mm
                wmma::mma_sync(acc, ah, bl, acc);   // hl
                wmma::mma_sync(acc, al, bh, acc);   // lh
            }

            // scoresT tile: [code_local(16)][xrow_local(16)] in warp scratch
            wmma::store_matrix_sync(swp, acc, SCLD, wmma::mem_row_major);
            __syncwarp();
            const int jb = g0 + nf * 16 + h * 8;
            #pragma unroll
            for (int j = 0; j < 8; j++) {
                float s = swp[(h * 8 + j) * SCLD + r] + n2a[jb + j];
                // strict >, indices ascend within lane sequence: first-max semantics
                if (s > best) { best = s; bidx = jb + j; }
            }
            __syncwarp();   // scan reads done before next nf's store overwrites
        }
    }

    // ---- merge lane pairs (h=1 -> h=0): (score, lower index) == global first-max ----
    {
        float ob = __shfl_down_sync(0xffffffffu, best, 1);
        int   oi = __shfl_down_sync(0xffffffffu, bidx, 1);
        if (h == 0) {
            if (ob > best || (ob == best && oi < bidx)) { best = ob; bidx = oi; }
            rw[wid * 16 + r] = bidx;
        }
    }
    __syncthreads();

    // ---- winners: cooperative coalesced gather ----
    const float4* eg = (const float4*)emb;
    float4* og = (float4*)(out + (size_t)row0 * D);
    for (int i = tid; i < MTILE * 16; i += TPB) {
        int rr = i >> 4, q = i & 15;
        og[rr * 16 + q] = eg[(size_t)rw[rr] * 16 + q];
    }
}

extern "C" void kernel_launch(void* const* d_in, const int* in_sizes, int n_in,
                              void* d_out, int out_size) {
    const float* x   = (const float*)d_in[0];
    const float* emb = (const float*)d_in[1];
    float* out = (float*)d_out;

    int nrows = in_sizes[0] / D;   // 262144, divisible by MTILE

    cudaFuncSetAttribute(vq_wmma_kernel,
                         cudaFuncAttributeMaxDynamicSharedMemorySize, SMEM_BYTES);

    vq_prep_kernel<<<(KC * D + TPB - 1) / TPB, TPB>>>(emb);

    int blocks = nrows / MTILE;    // 2048
    vq_wmma_kernel<<<blocks, TPB, SMEM_BYTES>>>(x, emb, out, nrows);
}

// round 17
// speedup vs baseline: 1.3093x; 1.3093x over previous
#include <cuda_runtime.h>
#include <cuda_bf16.h>
#include <mma.h>
#include <cstdint>

using namespace nvcuda;

#define D 64
#define KC 400
#define MTILE 128
#define NCH 80
#define NCHUNKS 5
#define TPB 256
#define XTLD 136        // bf16 ld for xT tiles [d][row]
#define ELD2 72         // bf16 ld for e tiles [code][d]
#define SLD 164         // f32 ld for scoresT [code][row]

// smem byte offsets
#define OFF_XTH 0                   // bf16[64][136] x3 (xT splits, persist)
#define OFF_XTM 17408
#define OFF_XTL 34816
#define OFF_UN  52224               // union: e tiles (3x11520) | scoresT f32[80][164]
#define OFF_EH  OFF_UN
#define OFF_EM  (OFF_UN + 11520)
#define OFF_EL  (OFF_UN + 23040)
#define OFF_SC  OFF_UN
#define OFF_N2A 104704              // f32[400]
#define OFF_RW  106304              // int[128]
#define SMEM_BYTES 106880

// precomputed e splits (h,m,l) and norms — __device__ scratch (allowed)
__device__ __nv_bfloat16 g_esp[3][KC * D];
__device__ float g_n2[KC];

// 3-way bf16 split: a ~= h + m + l (each captures ~8 mantissa bits)
static __device__ __forceinline__ void split3(float a, __nv_bfloat16 &h,
                                              __nv_bfloat16 &m, __nv_bfloat16 &l) {
    h = __float2bfloat16(a);
    float r = a - __bfloat162float(h);
    m = __float2bfloat16(r);
    float r2 = r - __bfloat162float(m);
    l = __float2bfloat16(r2);
}

__global__ void vq_prep_kernel(const float* __restrict__ emb) {
    int i = blockIdx.x * blockDim.x + threadIdx.x;
    if (i < KC * D) {
        __nv_bfloat16 h, m, l;
        split3(emb[i], h, m, l);
        g_esp[0][i] = h;
        g_esp[1][i] = m;
        g_esp[2][i] = l;
    }
    if (i < KC) {
        const float* e = emb + (size_t)i * D;
        float s = 0.f;
        #pragma unroll 16
        for (int d = 0; d < D; d++) s = fmaf(e[d], e[d], s);
        g_n2[i] = -0.5f * s;
    }
}

static __device__ __forceinline__ uint32_t smem_u32(const void* p) {
    uint32_t a;
    asm("{ .reg .u64 t; cvta.to.shared.u64 t, %1; cvt.u32.u64 %0, t; }" : "=r"(a) : "l"(p));
    return a;
}

__global__ void __launch_bounds__(TPB, 2)
vq_wmma_kernel(const float* __restrict__ x, const float* __restrict__ emb,
               float* __restrict__ out, int nrows) {
    extern __shared__ char sm[];
    float* n2a = (float*)(sm + OFF_N2A);
    int*   rw  = (int*)(sm + OFF_RW);
    float* sc  = (float*)(sm + OFF_SC);
    const uint32_t sb = smem_u32(sm);

    const int tid = threadIdx.x;
    const int wid = tid >> 5;
    const int lane = tid & 31;
    const int row0 = blockIdx.x * MTILE;

    // ---- norms to smem (precomputed) ----
    for (int i = tid; i < KC; i += TPB) n2a[i] = g_n2[i];

    // ---- stage xT once: [d][row] x3 splits; row-inner -> coalesced STS ----
    {
        const float4* xg = (const float4*)(x + (size_t)row0 * D);
        __nv_bfloat16* xth = (__nv_bfloat16*)(sm + OFF_XTH);
        __nv_bfloat16* xtm = (__nv_bfloat16*)(sm + OFF_XTM);
        __nv_bfloat16* xtl = (__nv_bfloat16*)(sm + OFF_XTL);
        for (int i = tid; i < MTILE * 16; i += TPB) {
            int row = i & 127, db = i >> 7;
            float4 v = xg[row * 16 + db];
            float vv[4] = {v.x, v.y, v.z, v.w};
            #pragma unroll
            for (int cc = 0; cc < 4; cc++) {
                __nv_bfloat16 h, m, l;
                split3(vv[cc], h, m, l);
                int o = (4 * db + cc) * XTLD + row;
                xth[o] = h; xtm[o] = m; xtl[o] = l;
            }
        }
    }

    // scan ownership: warp wid owns x-rows wid*16..+15 (its own score columns)
    const int r = lane >> 1;      // row-in-warp 0..15
    const int h = lane & 1;       // code half (40 each)
    float best = -3.4e38f;
    int bidx = 0;

    const __nv_bfloat16* eh  = (const __nv_bfloat16*)(sm + OFF_EH);
    const __nv_bfloat16* em  = (const __nv_bfloat16*)(sm + OFF_EM);
    const __nv_bfloat16* el  = (const __nv_bfloat16*)(sm + OFF_EL);
    const __nv_bfloat16* xth = (const __nv_bfloat16*)(sm + OFF_XTH) + wid * 16;
    const __nv_bfloat16* xtm = (const __nv_bfloat16*)(sm + OFF_XTM) + wid * 16;
    const __nv_bfloat16* xtl = (const __nv_bfloat16*)(sm + OFF_XTL) + wid * 16;

    for (int c = 0; c < NCHUNKS; c++) {
        const int g0 = c * NCH;
        __syncthreads();   // all scans done before staging overwrites union

        // ---- stage e chunk: cp.async 16B copies of precomputed splits (L2 -> smem) ----
        for (int i = tid; i < 3 * NCH * 8; i += TPB) {
            int split = i / (NCH * 8);
            int idx = i - split * (NCH * 8);
            int code = idx >> 3, c8 = idx & 7;
            const void* gp = &g_esp[split][(size_t)(g0 + code) * D + c8 * 8];
            uint32_t dst = sb + OFF_EH + split * 11520 + (code * ELD2 + c8 * 8) * 2;
            asm volatile("cp.async.cg.shared.global [%0], [%1], 16;" :: "r"(dst), "l"(gp));
        }
        asm volatile("cp.async.commit_group;");
        asm volatile("cp.async.wait_group 0;" ::: "memory");
        __syncthreads();

        // ---- MMAs: k-outer, 5 parallel acc chains (R15-proven structure) ----
        wmma::fragment<wmma::accumulator, 16, 16, 16, float> acc[5];
        #pragma unroll
        for (int nf = 0; nf < 5; nf++) wmma::fill_fragment(acc[nf], 0.0f);

        #pragma unroll
        for (int k = 0; k < 4; k++) {
            wmma::fragment<wmma::matrix_b, 16, 16, 16, __nv_bfloat16, wmma::row_major> bh, bm, bl;
            wmma::load_matrix_sync(bh, xth + k * 16 * XTLD, XTLD);
            wmma::load_matrix_sync(bm, xtm + k * 16 * XTLD, XTLD);
            wmma::load_matrix_sync(bl, xtl + k * 16 * XTLD, XTLD);
            #pragma unroll
            for (int nf = 0; nf < 5; nf++) {
                wmma::fragment<wmma::matrix_a, 16, 16, 16, __nv_bfloat16, wmma::row_major> ah, am, al;
                wmma::load_matrix_sync(ah, eh + nf * 16 * ELD2 + k * 16, ELD2);
                wmma::load_matrix_sync(am, em + nf * 16 * ELD2 + k * 16, ELD2);
                wmma::load_matrix_sync(al, el + nf * 16 * ELD2 + k * 16, ELD2);
                wmma::mma_sync(acc[nf], ah, bh, acc[nf]);   // hh
                wmma::mma_sync(acc[nf], ah, bm, acc[nf]);   // hm
                wmma::mma_sync(acc[nf], am, bh, acc[nf]);   // mh
                wmma::mma_sync(acc[nf], am, bm, acc[nf]);   // mm
                wmma::mma_sync(acc[nf], ah, bl, acc[nf]);   // hl
                wmma::mma_sync(acc[nf], al, bh, acc[nf]);   // lh
            }
        }

        __syncthreads();   // ALL warps done reading e before scores overwrite union

        // ---- store scoresT (warp's own 16 columns), then WARP-LOCAL scan ----
        #pragma unroll
        for (int nf = 0; nf < 5; nf++)
            wmma::store_matrix_sync(sc + nf * 16 * SLD + wid * 16, acc[nf], SLD,
                                    wmma::mem_row_major);
        __syncwarp();      // warp reads only its own columns: no block sync needed

        {
            const float* scol = sc + wid * 16 + r;
            const int jb = h * 40;
            #pragma unroll 8
            for (int j = 0; j < 40; j++) {
                int jj = jb + j;
                float s = scol[jj * SLD] + n2a[g0 + jj];
                // strict >, ascending jj within subsequence: first-max kept
                if (s > best) { best = s; bidx = g0 + jj; }
            }
        }
    }

    // ---- merge lane pairs (h=1 -> h=0): (score, lower index) == global first-max ----
    {
        float ob = __shfl_down_sync(0xffffffffu, best, 1);
        int   oi = __shfl_down_sync(0xffffffffu, bidx, 1);
        if (h == 0) {
            if (ob > best || (ob == best && oi < bidx)) { best = ob; bidx = oi; }
            rw[wid * 16 + r] = bidx;
        }
    }
    __syncthreads();

    // ---- winners: cooperative coalesced gather ----
    const float4* eg = (const float4*)emb;
    float4* og = (float4*)(out + (size_t)row0 * D);
    for (int i = tid; i < MTILE * 16; i += TPB) {
        int rr = i >> 4, q = i & 15;
        og[rr * 16 + q] = eg[(size_t)rw[rr] * 16 + q];
    }
}

extern "C" void kernel_launch(void* const* d_in, const int* in_sizes, int n_in,
                              void* d_out, int out_size) {
    const float* x   = (const float*)d_in[0];
    const float* emb = (const float*)d_in[1];
    float* out = (float*)d_out;

    int nrows = in_sizes[0] / D;   // 262144, divisible by MTILE

    cudaFuncSetAttribute(vq_wmma_kernel,
                         cudaFuncAttributeMaxDynamicSharedMemorySize, SMEM_BYTES);

    vq_prep_kernel<<<(KC * D + TPB - 1) / TPB, TPB>>>(emb);

    int blocks = nrows / MTILE;    // 2048
    vq_wmma_kernel<<<blocks, TPB, SMEM_BYTES>>>(x, emb, out, nrows);
}